// round 1
// baseline (speedup 1.0000x reference)
#include <cuda_runtime.h>
#include <math.h>

#define BB 4
#define CC 64
#define OCH 64
#define HH 256
#define WW 256
#define PP 64          // pixels per block (one 64-wide row strip)
#define NBLK (BB * HH * (WW / PP))   // 4096 blocks

// ---------------- device scratch (allowed: __device__ globals) -------------
__device__ float g_psum  [OCH * NBLK];
__device__ float g_psumsq[OCH * NBLK];
__device__ float g_scale [OCH];
__device__ float g_shift [OCH];

// shared memory layout (floats)
#define SM_PW   0                 // 192*64 = 12288
#define SM_W2   (SM_PW + 12288)   // 64*64  = 4096
#define SM_DW   (SM_W2 + 4096)    // 576
#define SM_BIAS (SM_DW + 576)     // 64
#define SM_T    (SM_BIAS + 64)    // 64*64 = 4096  (reused as sampled*mod)
#define SM_OFF  (SM_T + 4096)     // 128*64 = 8192
#define SM_MOD  (SM_OFF + 8192)   // 64*64 = 4096
#define SM_TOTF (SM_MOD + 4096)   // 33408 floats
#define SMEM_BYTES (SM_TOTF * 4)  // 133632 B

__device__ __forceinline__ float fetch_px(const float* __restrict__ img, int y, int x) {
    if ((unsigned)y < (unsigned)HH && (unsigned)x < (unsigned)WW)
        return __ldg(img + y * WW + x);
    return 0.0f;
}

__global__ __launch_bounds__(256)
void fused_deform_kernel(const float* __restrict__ x,
                         const float* __restrict__ dw,
                         const float* __restrict__ pw,
                         const float* __restrict__ w2,
                         const float* __restrict__ bias,
                         float* __restrict__ out)
{
    extern __shared__ float sm[];
    float* s_pw   = sm + SM_PW;
    float* s_w2   = sm + SM_W2;
    float* s_dw   = sm + SM_DW;
    float* s_bias = sm + SM_BIAS;
    float* s_t    = sm + SM_T;    // t[c][p], later sampled*mod
    float* s_off  = sm + SM_OFF;  // clipped om[0..127][p]
    float* s_mod  = sm + SM_MOD;  // 2*sigmoid(om[128+c])[p]

    const int tid = threadIdx.x;
    const int w0  = blockIdx.x * PP;
    const int h   = blockIdx.y;
    const int b   = blockIdx.z;
    const int bid = (blockIdx.z * gridDim.y + blockIdx.y) * gridDim.x + blockIdx.x;

    // ---- cooperative weight loads into smem -------------------------------
    for (int i = tid; i < 12288; i += 256) s_pw[i] = pw[i];
    for (int i = tid; i < 4096;  i += 256) s_w2[i] = w2[i];
    for (int i = tid; i < 576;   i += 256) s_dw[i] = dw[i];
    if (tid < 64) s_bias[tid] = bias[tid];
    __syncthreads();

    // ---- stage 1: depthwise 3x3 conv -> s_t[c][p] -------------------------
    const int p    = tid & 63;
    const int cg   = tid >> 6;       // 0..3
    const int wcol = w0 + p;
    {
        #pragma unroll 4
        for (int k = 0; k < 16; k++) {
            const int c = cg * 16 + k;
            const float* xc = x + ((size_t)(b * CC + c)) * (HH * WW);
            float acc = 0.0f;
            #pragma unroll
            for (int dy = -1; dy <= 1; dy++) {
                const int y = h + dy;
                if ((unsigned)y < (unsigned)HH) {
                    const float* row = xc + y * WW;
                    #pragma unroll
                    for (int dx = -1; dx <= 1; dx++) {
                        const int xx = wcol + dx;
                        if ((unsigned)xx < (unsigned)WW)
                            acc += s_dw[c * 9 + (dy + 1) * 3 + (dx + 1)] * __ldg(row + xx);
                    }
                }
            }
            s_t[c * 64 + p] = acc;
        }
    }
    __syncthreads();

    // ---- stage 2: 1x1 conv (192x64 matvec per pixel) ----------------------
    // thread tile: 4 j-rows x 4 pixels
    const int pq = tid & 15;
    const int p0 = pq * 4;
    const int jg = tid >> 4;         // 0..15
    #pragma unroll
    for (int pass = 0; pass < 3; pass++) {
        const int j0 = (jg + 16 * pass) * 4;
        float acc[4][4] = {{0,0,0,0},{0,0,0,0},{0,0,0,0},{0,0,0,0}};
        #pragma unroll 4
        for (int c = 0; c < 64; c++) {
            const float4 tv = *reinterpret_cast<const float4*>(&s_t[c * 64 + p0]);
            #pragma unroll
            for (int q = 0; q < 4; q++) {
                const float wv = s_pw[(j0 + q) * 64 + c];
                acc[q][0] += wv * tv.x;
                acc[q][1] += wv * tv.y;
                acc[q][2] += wv * tv.z;
                acc[q][3] += wv * tv.w;
            }
        }
        #pragma unroll
        for (int q = 0; q < 4; q++) {
            const int j = j0 + q;
            if (pass < 2) {          // j in [0,128): offsets, clipped to +-64
                #pragma unroll
                for (int r = 0; r < 4; r++)
                    s_off[j * 64 + p0 + r] = fminf(fmaxf(acc[q][r], -64.0f), 64.0f);
            } else {                 // j in [128,192): modulator = 2*sigmoid
                #pragma unroll
                for (int r = 0; r < 4; r++)
                    s_mod[(j - 128) * 64 + p0 + r] = 2.0f / (1.0f + expf(-acc[q][r]));
            }
        }
    }
    __syncthreads();

    // ---- stage 3: bilinear deformable sample * modulator -> s_t -----------
    // NOTE reshape quirk: channel c uses om channels 2c (y) and 2c+1 (x)
    {
        #pragma unroll 4
        for (int k = 0; k < 16; k++) {
            const int c = cg * 16 + k;
            const float offy = s_off[(2 * c)     * 64 + p];
            const float offx = s_off[(2 * c + 1) * 64 + p];
            const float sy = (float)h    + offy;
            const float sx = (float)wcol + offx;
            const float y0f = floorf(sy);
            const float x0f = floorf(sx);
            const float wy = sy - y0f;
            const float wx = sx - x0f;
            const int y0 = (int)y0f;
            const int x0 = (int)x0f;
            const float* xc = x + ((size_t)(b * CC + c)) * (HH * WW);
            const float v00 = fetch_px(xc, y0,     x0);
            const float v01 = fetch_px(xc, y0,     x0 + 1);
            const float v10 = fetch_px(xc, y0 + 1, x0);
            const float v11 = fetch_px(xc, y0 + 1, x0 + 1);
            const float val = (1.0f - wy) * ((1.0f - wx) * v00 + wx * v01)
                            +         wy  * ((1.0f - wx) * v10 + wx * v11);
            s_t[c * 64 + p] = val * s_mod[c * 64 + p];
        }
    }
    __syncthreads();

    // ---- stage 4: einsum (64x64 matvec) + bias + partial BN sums ----------
    {
        const int og = tid >> 4;     // 0..15
        const int o0 = og * 4;
        float acc[4][4] = {{0,0,0,0},{0,0,0,0},{0,0,0,0},{0,0,0,0}};
        #pragma unroll 4
        for (int c = 0; c < 64; c++) {
            const float4 sv = *reinterpret_cast<const float4*>(&s_t[c * 64 + p0]);
            #pragma unroll
            for (int q = 0; q < 4; q++) {
                const float wv = s_w2[(o0 + q) * 64 + c];
                acc[q][0] += wv * sv.x;
                acc[q][1] += wv * sv.y;
                acc[q][2] += wv * sv.z;
                acc[q][3] += wv * sv.w;
            }
        }
        #pragma unroll
        for (int q = 0; q < 4; q++) {
            const int o = o0 + q;
            const float bz = s_bias[o];
            float4 ov;
            ov.x = acc[q][0] + bz;
            ov.y = acc[q][1] + bz;
            ov.z = acc[q][2] + bz;
            ov.w = acc[q][3] + bz;
            float* op = out + (((size_t)(b * OCH + o)) * HH + h) * WW + w0 + p0;
            *reinterpret_cast<float4*>(op) = ov;

            float s  = ov.x + ov.y + ov.z + ov.w;
            float s2 = ov.x * ov.x + ov.y * ov.y + ov.z * ov.z + ov.w * ov.w;
            // reduce across the 16 lanes (pq) of this half-warp -> full strip sum
            #pragma unroll
            for (int m = 8; m >= 1; m >>= 1) {
                s  += __shfl_xor_sync(0xffffffffu, s,  m);
                s2 += __shfl_xor_sync(0xffffffffu, s2, m);
            }
            if (pq == 0) {
                g_psum  [o * NBLK + bid] = s;
                g_psumsq[o * NBLK + bid] = s2;
            }
        }
    }
}

// ---- reduce partials -> per-channel scale/shift (deterministic) -----------
__global__ void finalize_stats(const float* __restrict__ gamma,
                               const float* __restrict__ beta)
{
    const int o = blockIdx.x;
    __shared__ float ss[256];
    __shared__ float ss2[256];
    float s = 0.0f, s2 = 0.0f;
    for (int i = threadIdx.x; i < NBLK; i += 256) {
        s  += g_psum  [o * NBLK + i];
        s2 += g_psumsq[o * NBLK + i];
    }
    ss[threadIdx.x] = s; ss2[threadIdx.x] = s2;
    __syncthreads();
    for (int st = 128; st > 0; st >>= 1) {
        if (threadIdx.x < st) {
            ss [threadIdx.x] += ss [threadIdx.x + st];
            ss2[threadIdx.x] += ss2[threadIdx.x + st];
        }
        __syncthreads();
    }
    if (threadIdx.x == 0) {
        const float N = (float)(BB * HH * WW);
        const float mean = ss[0] / N;
        const float var  = ss2[0] / N - mean * mean;
        const float inv  = rsqrtf(var + 1e-5f);
        const float sc   = gamma[o] * inv;
        g_scale[o] = sc;
        g_shift[o] = beta[o] - mean * sc;
    }
}

// ---- in-place BN affine + exact GELU --------------------------------------
__device__ __forceinline__ float gelu_exact(float v) {
    return v * normcdff(v);
}

__global__ __launch_bounds__(256)
void bn_gelu_kernel(float* __restrict__ out)
{
    const int i = blockIdx.x * blockDim.x + threadIdx.x;   // float4 index
    float4 v = reinterpret_cast<float4*>(out)[i];
    const int o = ((i * 4) >> 16) & 63;                    // plane = HW = 65536
    const float sc = g_scale[o];
    const float sh = g_shift[o];
    v.x = gelu_exact(v.x * sc + sh);
    v.y = gelu_exact(v.y * sc + sh);
    v.z = gelu_exact(v.z * sc + sh);
    v.w = gelu_exact(v.w * sc + sh);
    reinterpret_cast<float4*>(out)[i] = v;
}

extern "C" void kernel_launch(void* const* d_in, const int* in_sizes, int n_in,
                              void* d_out, int out_size)
{
    const float* x     = (const float*)d_in[0];
    const float* dww   = (const float*)d_in[1];
    const float* pww   = (const float*)d_in[2];
    const float* w2    = (const float*)d_in[3];
    const float* bias  = (const float*)d_in[4];
    const float* gamma = (const float*)d_in[5];
    const float* beta  = (const float*)d_in[6];
    float* out = (float*)d_out;

    cudaFuncSetAttribute(fused_deform_kernel,
                         cudaFuncAttributeMaxDynamicSharedMemorySize, SMEM_BYTES);

    dim3 grid(WW / PP, HH, BB);
    fused_deform_kernel<<<grid, 256, SMEM_BYTES>>>(x, dww, pww, w2, bias, out);
    finalize_stats<<<OCH, 256>>>(gamma, beta);

    const int n4 = (BB * OCH * HH * WW) / 4;
    bn_gelu_kernel<<<n4 / 256, 256>>>(out);
}

// round 2
// speedup vs baseline: 2.1261x; 2.1261x over previous
#include <cuda_runtime.h>
#include <math.h>

#define BB 4
#define CC 64
#define OCH 64
#define HH 256
#define WW 256
#define PP 64
#define NBLK (BB * HH * (WW / PP))   // 4096 blocks

__device__ float g_psum  [OCH * NBLK];
__device__ float g_psumsq[OCH * NBLK];
__device__ float g_scale [OCH];
__device__ float g_shift [OCH];

__device__ __forceinline__ float fetch_px(const float* __restrict__ img, int y, int x) {
    if ((unsigned)y < (unsigned)HH && (unsigned)x < (unsigned)WW)
        return __ldg(img + y * WW + x);
    return 0.0f;
}

__global__ __launch_bounds__(256, 3)
void fused_deform_kernel(const float* __restrict__ x,
                         const float* __restrict__ dw,
                         const float* __restrict__ pw,
                         const float* __restrict__ w2,
                         const float* __restrict__ bias,
                         float* __restrict__ out)
{
    __shared__ float s_t   [CC * PP];   // dwconv output  t[c][p]   (16 KB)
    __shared__ float s_samp[CC * PP];   // sampled*mod    s[c][p]   (16 KB)

    const int tid = threadIdx.x;
    const int w0  = blockIdx.x * PP;
    const int h   = blockIdx.y;
    const int b   = blockIdx.z;
    const int bid = (blockIdx.z * gridDim.y + blockIdx.y) * gridDim.x + blockIdx.x;

    // ---- stage 1: depthwise 3x3 conv -> s_t[c][p] -------------------------
    {
        const int p    = tid & 63;
        const int cg   = tid >> 6;       // 0..3
        const int wcol = w0 + p;
        #pragma unroll 4
        for (int k = 0; k < 16; k++) {
            const int c = cg * 16 + k;
            const float* xc = x + ((size_t)(b * CC + c)) * (HH * WW);
            float acc = 0.0f;
            #pragma unroll
            for (int dy = -1; dy <= 1; dy++) {
                const int y = h + dy;
                if ((unsigned)y < (unsigned)HH) {
                    const float* row = xc + y * WW;
                    #pragma unroll
                    for (int dx = -1; dx <= 1; dx++) {
                        const int xx = wcol + dx;
                        if ((unsigned)xx < (unsigned)WW)
                            acc += __ldg(dw + c * 9 + (dy + 1) * 3 + (dx + 1)) * __ldg(row + xx);
                    }
                }
            }
            s_t[c * 64 + p] = acc;
        }
    }
    __syncthreads();

    // ---- stage 2: offset matvec (8 j-rows) + modulator matvec (4 j-rows),
    //      all register-resident, then bilinear sampling --------------------
    const int pq = tid & 15;
    const int p0 = pq * 4;
    const int jg = tid >> 4;             // 0..15
    const int c0 = jg * 4;               // this thread owns channels c0..c0+3

    // pass A: j = jg*8 .. jg*8+7  (om channels [0,128) = offsets)
    float accA[8][4];
    #pragma unroll
    for (int q = 0; q < 8; q++)
        #pragma unroll
        for (int r = 0; r < 4; r++) accA[q][r] = 0.0f;

    const float4* pw4 = (const float4*)pw;
    #pragma unroll 4
    for (int c4 = 0; c4 < 64; c4 += 4) {
        float4 tv0 = *reinterpret_cast<const float4*>(&s_t[(c4 + 0) * 64 + p0]);
        float4 tv1 = *reinterpret_cast<const float4*>(&s_t[(c4 + 1) * 64 + p0]);
        float4 tv2 = *reinterpret_cast<const float4*>(&s_t[(c4 + 2) * 64 + p0]);
        float4 tv3 = *reinterpret_cast<const float4*>(&s_t[(c4 + 3) * 64 + p0]);
        #pragma unroll
        for (int q = 0; q < 8; q++) {
            const float4 wv = __ldg(&pw4[((jg * 8 + q) * 64 + c4) >> 2]);
            accA[q][0] += wv.x * tv0.x + wv.y * tv1.x + wv.z * tv2.x + wv.w * tv3.x;
            accA[q][1] += wv.x * tv0.y + wv.y * tv1.y + wv.z * tv2.y + wv.w * tv3.y;
            accA[q][2] += wv.x * tv0.z + wv.y * tv1.z + wv.z * tv2.z + wv.w * tv3.z;
            accA[q][3] += wv.x * tv0.w + wv.y * tv1.w + wv.z * tv2.w + wv.w * tv3.w;
        }
    }

    // pass B: j = 128 + jg*4 .. +3  (modulator for channels c0..c0+3)
    float mod[4][4];
    {
        float accM[4][4];
        #pragma unroll
        for (int q = 0; q < 4; q++)
            #pragma unroll
            for (int r = 0; r < 4; r++) accM[q][r] = 0.0f;
        #pragma unroll 4
        for (int c4 = 0; c4 < 64; c4 += 4) {
            float4 tv0 = *reinterpret_cast<const float4*>(&s_t[(c4 + 0) * 64 + p0]);
            float4 tv1 = *reinterpret_cast<const float4*>(&s_t[(c4 + 1) * 64 + p0]);
            float4 tv2 = *reinterpret_cast<const float4*>(&s_t[(c4 + 2) * 64 + p0]);
            float4 tv3 = *reinterpret_cast<const float4*>(&s_t[(c4 + 3) * 64 + p0]);
            #pragma unroll
            for (int q = 0; q < 4; q++) {
                const float4 wv = __ldg(&pw4[((128 + jg * 4 + q) * 64 + c4) >> 2]);
                accM[q][0] += wv.x * tv0.x + wv.y * tv1.x + wv.z * tv2.x + wv.w * tv3.x;
                accM[q][1] += wv.x * tv0.y + wv.y * tv1.y + wv.z * tv2.y + wv.w * tv3.y;
                accM[q][2] += wv.x * tv0.z + wv.y * tv1.z + wv.z * tv2.z + wv.w * tv3.z;
                accM[q][3] += wv.x * tv0.w + wv.y * tv1.w + wv.z * tv2.w + wv.w * tv3.w;
            }
        }
        #pragma unroll
        for (int q = 0; q < 4; q++)
            #pragma unroll
            for (int r = 0; r < 4; r++)
                mod[q][r] = 2.0f / (1.0f + expf(-accM[q][r]));
    }

    // sampling: channel c0+i uses offsets (accA[2i], accA[2i+1]) clipped to +-64
    #pragma unroll
    for (int i = 0; i < 4; i++) {
        const int c = c0 + i;
        const float* xc = x + ((size_t)(b * CC + c)) * (HH * WW);
        float4 sv;
        float* svp = &sv.x;
        #pragma unroll
        for (int r = 0; r < 4; r++) {
            const float offy = fminf(fmaxf(accA[2 * i][r],     -64.0f), 64.0f);
            const float offx = fminf(fmaxf(accA[2 * i + 1][r], -64.0f), 64.0f);
            const float sy = (float)h + offy;
            const float sx = (float)(w0 + p0 + r) + offx;
            const float y0f = floorf(sy);
            const float x0f = floorf(sx);
            const float wy = sy - y0f;
            const float wx = sx - x0f;
            const int y0 = (int)y0f;
            const int x0i = (int)x0f;
            const float v00 = fetch_px(xc, y0,     x0i);
            const float v01 = fetch_px(xc, y0,     x0i + 1);
            const float v10 = fetch_px(xc, y0 + 1, x0i);
            const float v11 = fetch_px(xc, y0 + 1, x0i + 1);
            const float val = (1.0f - wy) * ((1.0f - wx) * v00 + wx * v01)
                            +         wy  * ((1.0f - wx) * v10 + wx * v11);
            svp[r] = val * mod[i][r];
        }
        *reinterpret_cast<float4*>(&s_samp[c * 64 + p0]) = sv;
    }
    __syncthreads();

    // ---- stage 4: einsum (64x64) + bias + partial BN sums -----------------
    {
        const int o0 = jg * 4;
        const float4* w24 = (const float4*)w2;
        float acc[4][4];
        #pragma unroll
        for (int q = 0; q < 4; q++)
            #pragma unroll
            for (int r = 0; r < 4; r++) acc[q][r] = 0.0f;
        #pragma unroll 4
        for (int c4 = 0; c4 < 64; c4 += 4) {
            float4 sv0 = *reinterpret_cast<const float4*>(&s_samp[(c4 + 0) * 64 + p0]);
            float4 sv1 = *reinterpret_cast<const float4*>(&s_samp[(c4 + 1) * 64 + p0]);
            float4 sv2 = *reinterpret_cast<const float4*>(&s_samp[(c4 + 2) * 64 + p0]);
            float4 sv3 = *reinterpret_cast<const float4*>(&s_samp[(c4 + 3) * 64 + p0]);
            #pragma unroll
            for (int q = 0; q < 4; q++) {
                const float4 wv = __ldg(&w24[((o0 + q) * 64 + c4) >> 2]);
                acc[q][0] += wv.x * sv0.x + wv.y * sv1.x + wv.z * sv2.x + wv.w * sv3.x;
                acc[q][1] += wv.x * sv0.y + wv.y * sv1.y + wv.z * sv2.y + wv.w * sv3.y;
                acc[q][2] += wv.x * sv0.z + wv.y * sv1.z + wv.z * sv2.z + wv.w * sv3.z;
                acc[q][3] += wv.x * sv0.w + wv.y * sv1.w + wv.z * sv2.w + wv.w * sv3.w;
            }
        }
        #pragma unroll
        for (int q = 0; q < 4; q++) {
            const int o = o0 + q;
            const float bz = __ldg(bias + o);
            float4 ov;
            ov.x = acc[q][0] + bz;
            ov.y = acc[q][1] + bz;
            ov.z = acc[q][2] + bz;
            ov.w = acc[q][3] + bz;
            float* op = out + (((size_t)(b * OCH + o)) * HH + h) * WW + w0 + p0;
            *reinterpret_cast<float4*>(op) = ov;

            float s  = ov.x + ov.y + ov.z + ov.w;
            float s2 = ov.x * ov.x + ov.y * ov.y + ov.z * ov.z + ov.w * ov.w;
            #pragma unroll
            for (int m = 8; m >= 1; m >>= 1) {
                s  += __shfl_xor_sync(0xffffffffu, s,  m);
                s2 += __shfl_xor_sync(0xffffffffu, s2, m);
            }
            if (pq == 0) {
                g_psum  [o * NBLK + bid] = s;
                g_psumsq[o * NBLK + bid] = s2;
            }
        }
    }
}

__global__ void finalize_stats(const float* __restrict__ gamma,
                               const float* __restrict__ beta)
{
    const int o = blockIdx.x;
    __shared__ float ss[256];
    __shared__ float ss2[256];
    float s = 0.0f, s2 = 0.0f;
    for (int i = threadIdx.x; i < NBLK; i += 256) {
        s  += g_psum  [o * NBLK + i];
        s2 += g_psumsq[o * NBLK + i];
    }
    ss[threadIdx.x] = s; ss2[threadIdx.x] = s2;
    __syncthreads();
    for (int st = 128; st > 0; st >>= 1) {
        if (threadIdx.x < st) {
            ss [threadIdx.x] += ss [threadIdx.x + st];
            ss2[threadIdx.x] += ss2[threadIdx.x + st];
        }
        __syncthreads();
    }
    if (threadIdx.x == 0) {
        const float N = (float)(BB * HH * WW);
        const float mean = ss[0] / N;
        const float var  = ss2[0] / N - mean * mean;
        const float inv  = rsqrtf(var + 1e-5f);
        const float sc   = gamma[o] * inv;
        g_scale[o] = sc;
        g_shift[o] = beta[o] - mean * sc;
    }
}

__device__ __forceinline__ float gelu_exact(float v) {
    return v * normcdff(v);
}

__global__ __launch_bounds__(256)
void bn_gelu_kernel(float* __restrict__ out)
{
    const int i = blockIdx.x * blockDim.x + threadIdx.x;   // float4 index
    float4 v = reinterpret_cast<float4*>(out)[i];
    const int o = ((i * 4) >> 16) & 63;                    // plane = HW = 65536
    const float sc = g_scale[o];
    const float sh = g_shift[o];
    v.x = gelu_exact(v.x * sc + sh);
    v.y = gelu_exact(v.y * sc + sh);
    v.z = gelu_exact(v.z * sc + sh);
    v.w = gelu_exact(v.w * sc + sh);
    reinterpret_cast<float4*>(out)[i] = v;
}

extern "C" void kernel_launch(void* const* d_in, const int* in_sizes, int n_in,
                              void* d_out, int out_size)
{
    const float* x     = (const float*)d_in[0];
    const float* dww   = (const float*)d_in[1];
    const float* pww   = (const float*)d_in[2];
    const float* w2    = (const float*)d_in[3];
    const float* bias  = (const float*)d_in[4];
    const float* gamma = (const float*)d_in[5];
    const float* beta  = (const float*)d_in[6];
    float* out = (float*)d_out;

    dim3 grid(WW / PP, HH, BB);
    fused_deform_kernel<<<grid, 256>>>(x, dww, pww, w2, bias, out);
    finalize_stats<<<OCH, 256>>>(gamma, beta);

    const int n4 = (BB * OCH * HH * WW) / 4;
    bn_gelu_kernel<<<n4 / 256, 256>>>(out);
}

// round 3
// speedup vs baseline: 2.3427x; 1.1018x over previous
#include <cuda_runtime.h>
#include <math.h>

#define BB 4
#define CC 64
#define OCH 64
#define HH 256
#define WW 256
#define PP 64
#define NBLK (BB * HH * (WW / PP))   // 4096 blocks

__device__ float g_psum  [OCH * NBLK];
__device__ float g_psumsq[OCH * NBLK];
__device__ float g_scale [OCH];
__device__ float g_shift [OCH];

__device__ __forceinline__ float fetch_px(const float* __restrict__ img, int y, int x) {
    if ((unsigned)y < (unsigned)HH && (unsigned)x < (unsigned)WW)
        return __ldg(img + y * WW + x);
    return 0.0f;
}

__global__ __launch_bounds__(256, 3)
void fused_deform_kernel(const float* __restrict__ x,
                         const float* __restrict__ dw,
                         const float* __restrict__ pw,
                         const float* __restrict__ w2,
                         const float* __restrict__ bias,
                         float* __restrict__ out)
{
    __shared__ float s_t   [CC * PP];   // dwconv output  t[c][p]   (16 KB)
    __shared__ float s_samp[CC * PP];   // sampled*mod    s[c][p]   (16 KB)

    const int tid = threadIdx.x;
    const int w0  = blockIdx.x * PP;
    const int h   = blockIdx.y;
    const int b   = blockIdx.z;
    const int bid = (blockIdx.z * gridDim.y + blockIdx.y) * gridDim.x + blockIdx.x;

    // ---- stage 1: depthwise 3x3 conv, vectorized: (channel, 4px) units ----
    {
        #pragma unroll
        for (int u = 0; u < 4; u++) {
            const int unit = tid + 256 * u;      // 0..1023
            const int c  = unit >> 4;            // 0..63
            const int g  = unit & 15;            // 0..15 (4-px group)
            const int xs = w0 + g * 4;           // start pixel (16B aligned)
            const float* xc = x + ((size_t)(b * CC + c)) * (HH * WW);
            float w9[9];
            #pragma unroll
            for (int i = 0; i < 9; i++) w9[i] = __ldg(dw + c * 9 + i);

            float a0 = 0.f, a1 = 0.f, a2 = 0.f, a3 = 0.f;
            #pragma unroll
            for (int dy = -1; dy <= 1; dy++) {
                const int y = h + dy;
                if ((unsigned)y < (unsigned)HH) {
                    const float* row = xc + y * WW;
                    const float4 m = *reinterpret_cast<const float4*>(row + xs);
                    const float lm = (xs - 1 >= 0) ? __ldg(row + xs - 1) : 0.0f;
                    const float rm = (xs + 4 < WW) ? __ldg(row + xs + 4) : 0.0f;
                    const float wl = w9[(dy + 1) * 3 + 0];
                    const float wm = w9[(dy + 1) * 3 + 1];
                    const float wr = w9[(dy + 1) * 3 + 2];
                    a0 += wl * lm  + wm * m.x + wr * m.y;
                    a1 += wl * m.x + wm * m.y + wr * m.z;
                    a2 += wl * m.y + wm * m.z + wr * m.w;
                    a3 += wl * m.z + wm * m.w + wr * rm;
                }
            }
            float4 r; r.x = a0; r.y = a1; r.z = a2; r.w = a3;
            *reinterpret_cast<float4*>(&s_t[c * 64 + g * 4]) = r;
        }
    }
    __syncthreads();

    // ---- stage 2: merged offset (8 rows) + modulator (4 rows) matvec ------
    const int pq = tid & 15;
    const int p0 = pq * 4;
    const int jg = tid >> 4;             // 0..15
    const int c0 = jg * 4;               // channels c0..c0+3 owned by thread

    float acc[12][4];                    // [0..7]=offset rows, [8..11]=mod rows
    #pragma unroll
    for (int q = 0; q < 12; q++)
        #pragma unroll
        for (int r = 0; r < 4; r++) acc[q][r] = 0.0f;

    const float4* pw4 = (const float4*)pw;
    #pragma unroll 4
    for (int c4 = 0; c4 < 64; c4 += 4) {
        const float4 tv0 = *reinterpret_cast<const float4*>(&s_t[(c4 + 0) * 64 + p0]);
        const float4 tv1 = *reinterpret_cast<const float4*>(&s_t[(c4 + 1) * 64 + p0]);
        const float4 tv2 = *reinterpret_cast<const float4*>(&s_t[(c4 + 2) * 64 + p0]);
        const float4 tv3 = *reinterpret_cast<const float4*>(&s_t[(c4 + 3) * 64 + p0]);
        #pragma unroll
        for (int q = 0; q < 8; q++) {
            const float4 wv = __ldg(&pw4[((jg * 8 + q) * 64 + c4) >> 2]);
            acc[q][0] += wv.x * tv0.x + wv.y * tv1.x + wv.z * tv2.x + wv.w * tv3.x;
            acc[q][1] += wv.x * tv0.y + wv.y * tv1.y + wv.z * tv2.y + wv.w * tv3.y;
            acc[q][2] += wv.x * tv0.z + wv.y * tv1.z + wv.z * tv2.z + wv.w * tv3.z;
            acc[q][3] += wv.x * tv0.w + wv.y * tv1.w + wv.z * tv2.w + wv.w * tv3.w;
        }
        #pragma unroll
        for (int q = 0; q < 4; q++) {
            const float4 wv = __ldg(&pw4[((128 + jg * 4 + q) * 64 + c4) >> 2]);
            acc[8 + q][0] += wv.x * tv0.x + wv.y * tv1.x + wv.z * tv2.x + wv.w * tv3.x;
            acc[8 + q][1] += wv.x * tv0.y + wv.y * tv1.y + wv.z * tv2.y + wv.w * tv3.y;
            acc[8 + q][2] += wv.x * tv0.z + wv.y * tv1.z + wv.z * tv2.z + wv.w * tv3.z;
            acc[8 + q][3] += wv.x * tv0.w + wv.y * tv1.w + wv.z * tv2.w + wv.w * tv3.w;
        }
    }

    // ---- stage 3: bilinear sampling * modulator -> s_samp -----------------
    // channel c0+i uses offset rows 2i (y) and 2i+1 (x), modulator row 8+i
    #pragma unroll
    for (int i = 0; i < 4; i++) {
        const int c = c0 + i;
        const float* xc = x + ((size_t)(b * CC + c)) * (HH * WW);
        float4 sv;
        float* svp = &sv.x;
        #pragma unroll
        for (int r = 0; r < 4; r++) {
            const float offy = fminf(fmaxf(acc[2 * i][r],     -64.0f), 64.0f);
            const float offx = fminf(fmaxf(acc[2 * i + 1][r], -64.0f), 64.0f);
            const float md   = 2.0f / (1.0f + expf(-acc[8 + i][r]));
            const float sy = (float)h + offy;
            const float sx = (float)(w0 + p0 + r) + offx;
            const float y0f = floorf(sy);
            const float x0f = floorf(sx);
            const float wy = sy - y0f;
            const float wx = sx - x0f;
            const int y0  = (int)y0f;
            const int x0i = (int)x0f;
            const float v00 = fetch_px(xc, y0,     x0i);
            const float v01 = fetch_px(xc, y0,     x0i + 1);
            const float v10 = fetch_px(xc, y0 + 1, x0i);
            const float v11 = fetch_px(xc, y0 + 1, x0i + 1);
            const float val = (1.0f - wy) * ((1.0f - wx) * v00 + wx * v01)
                            +         wy  * ((1.0f - wx) * v10 + wx * v11);
            svp[r] = val * md;
        }
        *reinterpret_cast<float4*>(&s_samp[c * 64 + p0]) = sv;
    }
    __syncthreads();

    // ---- stage 4: einsum (64x64) + bias + partial BN sums -----------------
    {
        const int o0 = jg * 4;
        const float4* w24 = (const float4*)w2;
        float ac4[4][4];
        #pragma unroll
        for (int q = 0; q < 4; q++)
            #pragma unroll
            for (int r = 0; r < 4; r++) ac4[q][r] = 0.0f;
        #pragma unroll 4
        for (int c4 = 0; c4 < 64; c4 += 4) {
            const float4 sv0 = *reinterpret_cast<const float4*>(&s_samp[(c4 + 0) * 64 + p0]);
            const float4 sv1 = *reinterpret_cast<const float4*>(&s_samp[(c4 + 1) * 64 + p0]);
            const float4 sv2 = *reinterpret_cast<const float4*>(&s_samp[(c4 + 2) * 64 + p0]);
            const float4 sv3 = *reinterpret_cast<const float4*>(&s_samp[(c4 + 3) * 64 + p0]);
            #pragma unroll
            for (int q = 0; q < 4; q++) {
                const float4 wv = __ldg(&w24[((o0 + q) * 64 + c4) >> 2]);
                ac4[q][0] += wv.x * sv0.x + wv.y * sv1.x + wv.z * sv2.x + wv.w * sv3.x;
                ac4[q][1] += wv.x * sv0.y + wv.y * sv1.y + wv.z * sv2.y + wv.w * sv3.y;
                ac4[q][2] += wv.x * sv0.z + wv.y * sv1.z + wv.z * sv2.z + wv.w * sv3.z;
                ac4[q][3] += wv.x * sv0.w + wv.y * sv1.w + wv.z * sv2.w + wv.w * sv3.w;
            }
        }
        #pragma unroll
        for (int q = 0; q < 4; q++) {
            const int o = o0 + q;
            const float bz = __ldg(bias + o);
            float4 ov;
            ov.x = ac4[q][0] + bz;
            ov.y = ac4[q][1] + bz;
            ov.z = ac4[q][2] + bz;
            ov.w = ac4[q][3] + bz;
            float* op = out + (((size_t)(b * OCH + o)) * HH + h) * WW + w0 + p0;
            *reinterpret_cast<float4*>(op) = ov;

            float s  = ov.x + ov.y + ov.z + ov.w;
            float s2 = ov.x * ov.x + ov.y * ov.y + ov.z * ov.z + ov.w * ov.w;
            #pragma unroll
            for (int m = 8; m >= 1; m >>= 1) {
                s  += __shfl_xor_sync(0xffffffffu, s,  m);
                s2 += __shfl_xor_sync(0xffffffffu, s2, m);
            }
            if (pq == 0) {
                g_psum  [o * NBLK + bid] = s;
                g_psumsq[o * NBLK + bid] = s2;
            }
        }
    }
}

__global__ void finalize_stats(const float* __restrict__ gamma,
                               const float* __restrict__ beta)
{
    const int o = blockIdx.x;
    __shared__ float ss[256];
    __shared__ float ss2[256];
    float s = 0.0f, s2 = 0.0f;
    for (int i = threadIdx.x; i < NBLK; i += 256) {
        s  += g_psum  [o * NBLK + i];
        s2 += g_psumsq[o * NBLK + i];
    }
    ss[threadIdx.x] = s; ss2[threadIdx.x] = s2;
    __syncthreads();
    for (int st = 128; st > 0; st >>= 1) {
        if (threadIdx.x < st) {
            ss [threadIdx.x] += ss [threadIdx.x + st];
            ss2[threadIdx.x] += ss2[threadIdx.x + st];
        }
        __syncthreads();
    }
    if (threadIdx.x == 0) {
        const float N = (float)(BB * HH * WW);
        const float mean = ss[0] / N;
        const float var  = ss2[0] / N - mean * mean;
        const float inv  = rsqrtf(var + 1e-5f);
        const float sc   = gamma[o] * inv;
        g_scale[o] = sc;
        g_shift[o] = beta[o] - mean * sc;
    }
}

__device__ __forceinline__ float gelu_exact(float v) {
    return v * normcdff(v);
}

__global__ __launch_bounds__(256)
void bn_gelu_kernel(float* __restrict__ out)
{
    const int i = blockIdx.x * blockDim.x + threadIdx.x;   // float4 index
    float4 v = reinterpret_cast<float4*>(out)[i];
    const int o = ((i * 4) >> 16) & 63;                    // plane = HW = 65536
    const float sc = g_scale[o];
    const float sh = g_shift[o];
    v.x = gelu_exact(v.x * sc + sh);
    v.y = gelu_exact(v.y * sc + sh);
    v.z = gelu_exact(v.z * sc + sh);
    v.w = gelu_exact(v.w * sc + sh);
    reinterpret_cast<float4*>(out)[i] = v;
}

extern "C" void kernel_launch(void* const* d_in, const int* in_sizes, int n_in,
                              void* d_out, int out_size)
{
    const float* x     = (const float*)d_in[0];
    const float* dww   = (const float*)d_in[1];
    const float* pww   = (const float*)d_in[2];
    const float* w2    = (const float*)d_in[3];
    const float* bias  = (const float*)d_in[4];
    const float* gamma = (const float*)d_in[5];
    const float* beta  = (const float*)d_in[6];
    float* out = (float*)d_out;

    dim3 grid(WW / PP, HH, BB);
    fused_deform_kernel<<<grid, 256>>>(x, dww, pww, w2, bias, out);
    finalize_stats<<<OCH, 256>>>(gamma, beta);

    const int n4 = (BB * OCH * HH * WW) / 4;
    bn_gelu_kernel<<<n4 / 256, 256>>>(out);
}